// round 3
// baseline (speedup 1.0000x reference)
#include <cuda_runtime.h>
#include <math.h>

// ---------------- constants ----------------
#define BB    16
#define DIMC  128
#define HDC   64
#define LL    3136      // 56*56
#define NTOK  49
#define NHEAD 8
#define DI_   128
#define DST_  16
#define DTR_  4
#define KDIR  4
#define CX    36        // DTR + 2*DST
#define HID4  512

// ---------------- scratch (static device memory; no allocations) ----------------
__device__ float g_tmp [BB*DI_*LL];        // mamba in-proj output (pre dwconv)
__device__ float g_xm  [BB*DI_*LL];        // mamba x after dwconv+silu
__device__ float g_xdbl[BB*KDIR*CX*LL];    // x_dbl projections (dt_raw, B, C) per direction
__device__ float g_ys  [(size_t)BB*KDIR*DI_*LL]; // scan outputs per direction
__device__ float g_y   [BB*DIMC*LL];       // concat(y_attn, y_mamba)
__device__ float g_pool[BB*DIMC];
__device__ float g_sse [BB*DIMC];
__device__ float g_xr  [BB*DIMC*LL];       // x + gamma1 * y * s
__device__ float g_h   [(size_t)BB*HID4*LL]; // MLP hidden

// ---------------- helpers ----------------
__device__ __forceinline__ float fgelu(float x){
    float u = 0.7978845608028654f*(x + 0.044715f*x*x*x);
    float t;
    asm("tanh.approx.f32 %0, %1;" : "=f"(t) : "f"(u));
    return 0.5f*x*(1.f+t);
}
__device__ __forceinline__ float fsoftplus(float x){
    return (x > 20.f) ? x : log1pf(__expf(x));
}
__device__ __forceinline__ float fsilu(float x){
    return x * (1.f/(1.f+__expf(-x)));
}

// ---------------- 1. window attention ----------------
// grid 1024 (one block per 7x7 window), 256 threads, dynamic smem ~78KB
__global__ void attn_kernel(const float* __restrict__ x,
    const float* __restrict__ wq, const float* __restrict__ wk, const float* __restrict__ wv,
    const float* __restrict__ wproj, const float* __restrict__ bproj,
    const float* __restrict__ gq, const float* __restrict__ gk, const float* __restrict__ gv)
{
    extern __shared__ float sm[];
    float* xw  = sm;                 // [49][65]  (reused as o-buffer later)
    float* qs  = xw + NTOK*65;
    float* ks  = qs + NTOK*65;
    float* vs  = ks + NTOK*65;
    float* ws  = vs + NTOK*65;       // [64][65]
    float* sc  = ws + 64*65;         // [49][52]
    float* inv = sc + NTOK*52;       // [49]

    int tid = threadIdx.x;
    int bw  = blockIdx.x;
    int b   = bw >> 6;
    int wh  = (bw >> 3) & 7;
    int wwi = bw & 7;
    int h0  = wh*7, w0 = wwi*7;
    const float* xb = x + (size_t)b*DIMC*LL;

    // load window (channels 0..63 of x)
    for (int i = tid; i < NTOK*64; i += blockDim.x){
        int c = i / NTOK, t = i - c*NTOK;
        int hh = h0 + t/7, ww2 = w0 + t%7;
        xw[t*65 + c] = xb[(size_t)c*LL + hh*56 + ww2];
    }
    __syncthreads();
    if (tid < NTOK){
        float ssum = 0.f;
        #pragma unroll
        for (int c = 0; c < 64; c++){ float v = xw[tid*65+c]; ssum += v*v; }
        inv[tid] = rsqrtf(ssum*(1.f/64.f) + 1e-5f);
    }
    __syncthreads();

    // q/k/v projections (rms gain folded into weights)
    for (int pj = 0; pj < 3; pj++){
        const float* W = (pj==0) ? wq : ((pj==1) ? wk : wv);
        const float* G = (pj==0) ? gq : ((pj==1) ? gk : gv);
        float* OUT     = (pj==0) ? qs : ((pj==1) ? ks : vs);
        for (int i = tid; i < 64*64; i += blockDim.x){
            int o = i >> 6, d2 = i & 63;
            ws[o*65 + d2] = W[o*64 + d2] * G[d2];
        }
        __syncthreads();
        for (int idx = tid; idx < NTOK*64; idx += blockDim.x){
            int i2 = idx >> 6, o = idx & 63;
            float acc = 0.f;
            #pragma unroll
            for (int d2 = 0; d2 < 64; d2++)
                acc = fmaf(xw[i2*65+d2], ws[o*65+d2], acc);
            OUT[i2*65 + o] = acc * inv[i2];
        }
        __syncthreads();
    }

    float* ob = xw;   // alias: raw window no longer needed
    for (int hh2 = 0; hh2 < NHEAD; hh2++){
        int hb = hh2*8;
        for (int idx = tid; idx < NTOK*NTOK; idx += blockDim.x){
            int i2 = idx / NTOK, j = idx - i2*NTOK;
            float acc = 0.f;
            #pragma unroll
            for (int dd = 0; dd < 8; dd++)
                acc = fmaf(qs[i2*65+hb+dd], ks[j*65+hb+dd], acc);
            sc[i2*52 + j] = acc * 0.35355339059327373f;
        }
        __syncthreads();
        if (tid < NTOK){
            float m = -1e30f;
            for (int j = 0; j < NTOK; j++) m = fmaxf(m, sc[tid*52+j]);
            float s = 0.f;
            for (int j = 0; j < NTOK; j++){ float e = __expf(sc[tid*52+j]-m); sc[tid*52+j] = e; s += e; }
            float r = 1.f/s;
            for (int j = 0; j < NTOK; j++) sc[tid*52+j] *= r;
        }
        __syncthreads();
        for (int idx = tid; idx < NTOK*8; idx += blockDim.x){
            int i2 = idx >> 3, dd = idx & 7;
            float acc = 0.f;
            for (int j = 0; j < NTOK; j++)
                acc = fmaf(sc[i2*52+j], vs[j*65+hb+dd], acc);
            ob[i2*65 + hb + dd] = acc;
        }
        __syncthreads();
    }

    // output projection + window reverse into g_y channels [0,64)
    for (int i = tid; i < 64*64; i += blockDim.x){
        int o = i >> 6, d2 = i & 63;
        ws[o*65 + d2] = wproj[o*64 + d2];
    }
    __syncthreads();
    for (int idx = tid; idx < NTOK*64; idx += blockDim.x){
        int o = idx / NTOK, i2 = idx - o*NTOK;
        float acc = bproj[o];
        #pragma unroll
        for (int d2 = 0; d2 < 64; d2++)
            acc = fmaf(ob[i2*65+d2], ws[o*65+d2], acc);
        int hh = h0 + i2/7, wcol = w0 + i2%7;
        g_y[((size_t)b*DIMC + o)*LL + hh*56 + wcol] = acc;
    }
}

// ---------------- 2a. rms2d + mamba in-projection ----------------
// grid 196, 256 threads
__global__ void rmsinproj_kernel(const float* __restrict__ x,
    const float* __restrict__ w_in, const float* __restrict__ gvm)
{
    __shared__ float ws[DI_*64];   // 32KB
    int tid = threadIdx.x;
    for (int i = tid; i < DI_*64; i += blockDim.x){
        int c = i & 63;
        ws[i] = w_in[i] * gvm[c];
    }
    __syncthreads();
    int gid = blockIdx.x*blockDim.x + tid;
    int b = gid / LL, p = gid - b*LL;
    const float* xb = x + ((size_t)b*DIMC + HDC)*LL + p;
    float xr[64];
    float ssum = 0.f;
    #pragma unroll
    for (int c = 0; c < 64; c++){ float v = xb[(size_t)c*LL]; xr[c] = v; ssum += v*v; }
    float inv = rsqrtf(ssum*(1.f/64.f) + 1e-5f);
    float* ob = g_tmp + (size_t)b*DI_*LL + p;
    for (int o = 0; o < DI_; o++){
        float acc = 0.f;
        #pragma unroll
        for (int c = 0; c < 64; c++) acc = fmaf(xr[c], ws[o*64+c], acc);
        ob[(size_t)o*LL] = acc*inv;
    }
}

// ---------------- 2b. depthwise 3x3 + bias + silu ----------------
// grid 25088, 256 threads
__global__ void dwconv_kernel(const float* __restrict__ cw, const float* __restrict__ cb)
{
    int gid = blockIdx.x*blockDim.x + threadIdx.x;   // over BB*DI_*LL
    int p  = gid % LL;
    int bc = gid / LL;
    int c  = bc % DI_;
    int h = p / 56, w = p - h*56;
    const float* xp = g_tmp + (size_t)bc*LL;
    const float* wc = cw + c*9;
    float acc = cb[c];
    #pragma unroll
    for (int ky = 0; ky < 3; ky++){
        int hy = h + ky - 1;
        if (hy < 0 || hy >= 56) continue;
        #pragma unroll
        for (int kx = 0; kx < 3; kx++){
            int wx = w + kx - 1;
            if (wx < 0 || wx >= 56) continue;
            acc = fmaf(xp[hy*56 + wx], wc[ky*3+kx], acc);
        }
    }
    g_xm[gid] = fsilu(acc);
}

// ---------------- 3a. x_dbl projections (dt_raw / B / C) for all 4 directions ----------------
// grid 196, 256 threads, dynamic smem 73728B
__global__ void xdbl_kernel(const float* __restrict__ xproj)
{
    extern __shared__ float wxs[];  // [K*CX][DI_]
    int tid = threadIdx.x;
    for (int i = tid; i < KDIR*CX*DI_; i += blockDim.x){
        int k = i / (CX*DI_);
        int rem = i - k*CX*DI_;
        int c = rem / DI_;
        int d = rem - c*DI_;
        wxs[i] = xproj[(k*DI_ + d)*CX + c];
    }
    __syncthreads();
    int gid = blockIdx.x*blockDim.x + tid;
    int b = gid / LL, p = gid - b*LL;
    float xr[DI_];
    const float* xb = g_xm + (size_t)b*DI_*LL + p;
    #pragma unroll
    for (int d = 0; d < DI_; d++) xr[d] = xb[(size_t)d*LL];
    int h = p / 56, w = p - h*56;
    int l1 = w*56 + h;
    int lk[4]; lk[0]=p; lk[1]=l1; lk[2]=LL-1-p; lk[3]=LL-1-l1;
    for (int k = 0; k < KDIR; k++){
        float* obp = g_xdbl + (size_t)(b*KDIR + k)*CX*LL + lk[k];
        const float* wk2 = wxs + k*CX*DI_;
        for (int c = 0; c < CX; c++){
            float acc = 0.f;
            #pragma unroll
            for (int d = 0; d < DI_; d++) acc = fmaf(xr[d], wk2[c*DI_ + d], acc);
            obp[(size_t)c*LL] = acc;
        }
    }
}

// ---------------- 3b. selective scan ----------------
// grid 128 (b,k,d-half), 128 threads (2 threads/channel, 8 states each)
__global__ void scan_kernel(const float* __restrict__ dtw, const float* __restrict__ dtb,
    const float* __restrict__ alog, const float* __restrict__ Dp)
{
    __shared__ float Uc[64*65];
    __shared__ float Pc[CX*65];
    __shared__ float Yc[64*65];
    int tid  = threadIdx.x;
    int blk  = blockIdx.x;
    int half = blk & 1;
    int bk   = blk >> 1;
    int k    = bk & 3;
    int b    = bk >> 2;
    int ch   = tid >> 1;
    int d    = half*64 + ch;
    int ng   = (tid & 1)*8;
    int kd   = k*DI_ + d;

    float dtw4[4];
    #pragma unroll
    for (int r = 0; r < 4; r++) dtw4[r] = dtw[kd*4 + r];
    float dtbv = dtb[kd];
    float Dd   = Dp[kd];
    float A2[8];
    #pragma unroll
    for (int n = 0; n < 8; n++) A2[n] = -__expf(alog[kd*DST_ + ng + n]);
    float hst[8];
    #pragma unroll
    for (int n = 0; n < 8; n++) hst[n] = 0.f;

    const float* xmb = g_xm + ((size_t)b*DI_ + half*64)*LL;
    const float* pdb = g_xdbl + (size_t)(b*KDIR + k)*CX*LL;
    float* yb = g_ys + ((size_t)(b*KDIR + k)*DI_ + half*64)*LL;

    for (int s0 = 0; s0 < LL; s0 += 64){
        for (int i = tid; i < 64*64; i += 128){
            int dd = i >> 6, t = i & 63;
            int s = s0 + t;
            int pq;
            if (k == 0)      pq = s;
            else if (k == 1) pq = (s % 56)*56 + s/56;
            else if (k == 2) pq = LL-1-s;
            else { int s2 = LL-1-s; pq = (s2 % 56)*56 + s2/56; }
            Uc[dd*65 + t] = xmb[(size_t)dd*LL + pq];
        }
        for (int i = tid; i < CX*64; i += 128){
            int c = i >> 6, t = i & 63;
            Pc[c*65 + t] = pdb[(size_t)c*LL + s0 + t];
        }
        __syncthreads();
        for (int t = 0; t < 64; t++){
            float dtr = dtbv;
            #pragma unroll
            for (int r = 0; r < 4; r++) dtr = fmaf(Pc[r*65 + t], dtw4[r], dtr);
            float delta = fsoftplus(dtr);
            float u  = Uc[ch*65 + t];
            float du = delta*u;
            float y = 0.f;
            #pragma unroll
            for (int n = 0; n < 8; n++){
                float Bv = Pc[(4  + ng + n)*65 + t];
                float Cv = Pc[(20 + ng + n)*65 + t];
                float pe = __expf(delta * A2[n]);
                hst[n] = fmaf(pe, hst[n], du*Bv);
                y = fmaf(hst[n], Cv, y);
            }
            y += __shfl_xor_sync(0xffffffffu, y, 1);
            if ((tid & 1) == 0) Yc[ch*65 + t] = fmaf(u, Dd, y);
        }
        __syncthreads();
        for (int i = tid; i < 64*64; i += 128){
            int dd = i >> 6, t = i & 63;
            yb[(size_t)dd*LL + s0 + t] = Yc[dd*65 + t];
        }
        __syncthreads();
    }
}

// ---------------- 4. cross_merge + gelu + out-projection ----------------
// grid 196, 256 threads
__global__ void merge_kernel(const float* __restrict__ wout)
{
    __shared__ float ws[HDC*DI_];   // 32KB
    int tid = threadIdx.x;
    for (int i = tid; i < HDC*DI_; i += blockDim.x) ws[i] = wout[i];
    __syncthreads();
    int gid = blockIdx.x*blockDim.x + tid;
    int b = gid / LL, p = gid - b*LL;
    int h = p/56, w = p - h*56;
    int l1 = w*56 + h;
    const float* y0 = g_ys + (size_t)(b*KDIR + 0)*DI_*LL;
    const float* y1 = g_ys + (size_t)(b*KDIR + 1)*DI_*LL;
    const float* y2 = g_ys + (size_t)(b*KDIR + 2)*DI_*LL;
    const float* y3 = g_ys + (size_t)(b*KDIR + 3)*DI_*LL;
    float ymg[DI_];
    #pragma unroll
    for (int d2 = 0; d2 < DI_; d2++){
        float v = y0[(size_t)d2*LL + p] + y2[(size_t)d2*LL + (LL-1-p)]
                + y1[(size_t)d2*LL + l1] + y3[(size_t)d2*LL + (LL-1-l1)];
        ymg[d2] = fgelu(v);
    }
    float* obp = g_y + ((size_t)b*DIMC + HDC)*LL + p;
    for (int o = 0; o < HDC; o++){
        float acc = 0.f;
        #pragma unroll
        for (int d2 = 0; d2 < DI_; d2++) acc = fmaf(ymg[d2], ws[o*DI_ + d2], acc);
        obp[(size_t)o*LL] = acc;
    }
}

// ---------------- 5a. global average pool ----------------
__global__ void pool_kernel(void)
{
    __shared__ float red[256];
    int bc = blockIdx.x;
    const float* yb = g_y + (size_t)bc*LL;
    float s = 0.f;
    for (int i = threadIdx.x; i < LL; i += 256) s += yb[i];
    red[threadIdx.x] = s;
    __syncthreads();
    for (int st = 128; st > 0; st >>= 1){
        if (threadIdx.x < st) red[threadIdx.x] += red[threadIdx.x + st];
        __syncthreads();
    }
    if (threadIdx.x == 0) g_pool[bc] = red[0]*(1.f/LL);
}

// ---------------- 5b. SE mlp ----------------
// 1 block, 128 threads
__global__ void se_kernel(const float* __restrict__ w1, const float* __restrict__ b1,
    const float* __restrict__ w2, const float* __restrict__ b2)
{
    __shared__ float pv[DIMC];
    __shared__ float h1[32];
    int tid = threadIdx.x;
    for (int b = 0; b < BB; b++){
        if (tid < DIMC) pv[tid] = g_pool[b*DIMC + tid];
        __syncthreads();
        if (tid < 32){
            float acc = b1[tid];
            #pragma unroll
            for (int c = 0; c < DIMC; c++) acc = fmaf(pv[c], w1[tid*DIMC + c], acc);
            h1[tid] = fmaxf(acc, 0.f);
        }
        __syncthreads();
        if (tid < DIMC){
            float acc = b2[tid];
            #pragma unroll
            for (int j = 0; j < 32; j++) acc = fmaf(h1[j], w2[tid*32 + j], acc);
            g_sse[b*DIMC + tid] = 1.f/(1.f + __expf(-acc));
        }
        __syncthreads();
    }
}

// ---------------- 5c. residual 1 ----------------
__global__ void resid1_kernel(const float* __restrict__ x, const float* __restrict__ gamma1)
{
    int gid = blockIdx.x*blockDim.x + threadIdx.x;   // over BB*DIMC*LL
    int bc = gid / LL;
    int c = bc % DIMC;
    g_xr[gid] = fmaf(gamma1[c]*g_sse[bc], g_y[gid], x[gid]);
}

// ---------------- 6a. rms2d + MLP fc1 + gelu ----------------
// grid 196, 256 threads
__global__ void mlp1_kernel(const float* __restrict__ gmlp,
    const float* __restrict__ w1, const float* __restrict__ b1)
{
    __shared__ float ws[64*DIMC];   // 32KB
    __shared__ float gsh[DIMC];
    int tid = threadIdx.x;
    if (tid < DIMC) gsh[tid] = gmlp[tid];
    __syncthreads();
    int gid = blockIdx.x*blockDim.x + tid;
    int b = gid / LL, p = gid - b*LL;
    float xn[DIMC];
    const float* xb = g_xr + (size_t)b*DIMC*LL + p;
    float ssum = 0.f;
    #pragma unroll
    for (int c = 0; c < DIMC; c++){ float v = xb[(size_t)c*LL]; xn[c] = v; ssum += v*v; }
    float inv = rsqrtf(ssum*(1.f/DIMC) + 1e-5f);
    #pragma unroll
    for (int c = 0; c < DIMC; c++) xn[c] *= inv*gsh[c];
    float* obp = g_h + (size_t)b*HID4*LL + p;
    for (int ck = 0; ck < 8; ck++){
        __syncthreads();
        for (int i = tid; i < 64*DIMC; i += blockDim.x) ws[i] = w1[ck*64*DIMC + i];
        __syncthreads();
        for (int oo = 0; oo < 64; oo++){
            int o = ck*64 + oo;
            float acc = b1[o];
            #pragma unroll
            for (int c = 0; c < DIMC; c++) acc = fmaf(xn[c], ws[oo*DIMC + c], acc);
            obp[(size_t)o*LL] = fgelu(acc);
        }
    }
}

// ---------------- 6b. MLP fc2 + residual 2 -> output ----------------
// grid 196, 256 threads
__global__ void mlp2_kernel(const float* __restrict__ w2, const float* __restrict__ b2,
    const float* __restrict__ gamma2, float* __restrict__ out)
{
    __shared__ float ws[64*129];
    int tid = threadIdx.x;
    int gid = blockIdx.x*blockDim.x + tid;
    int b = gid / LL, p = gid - b*LL;
    float acc[DIMC];
    #pragma unroll
    for (int o = 0; o < DIMC; o++) acc[o] = 0.f;
    const float* hb = g_h + (size_t)b*HID4*LL + p;
    for (int ck = 0; ck < 8; ck++){
        __syncthreads();
        for (int i = tid; i < 64*DIMC; i += blockDim.x){
            int o = i >> 6, jj = i & 63;
            ws[jj*129 + o] = w2[o*HID4 + ck*64 + jj];
        }
        __syncthreads();
        #pragma unroll 4
        for (int jj = 0; jj < 64; jj++){
            float hv = hb[(size_t)(ck*64 + jj)*LL];
            #pragma unroll
            for (int o = 0; o < DIMC; o++) acc[o] = fmaf(hv, ws[jj*129 + o], acc[o]);
        }
    }
    const float* xb = g_xr + (size_t)b*DIMC*LL + p;
    float* obp = out + (size_t)b*DIMC*LL + p;
    #pragma unroll
    for (int o = 0; o < DIMC; o++)
        obp[(size_t)o*LL] = fmaf(gamma2[o], acc[o] + b2[o], xb[(size_t)o*LL]);
}

// ---------------- launch ----------------
extern "C" void kernel_launch(void* const* d_in, const int* in_sizes, int n_in,
                              void* d_out, int out_size)
{
    const float* x      = (const float*)d_in[0];
    const float* wq     = (const float*)d_in[1];
    const float* wk     = (const float*)d_in[2];
    const float* wv     = (const float*)d_in[3];
    const float* wproj  = (const float*)d_in[4];
    const float* bproj  = (const float*)d_in[5];
    const float* gq     = (const float*)d_in[6];
    const float* gk     = (const float*)d_in[7];
    const float* gv     = (const float*)d_in[8];
    const float* gvm    = (const float*)d_in[9];
    const float* gmlp   = (const float*)d_in[10];
    const float* m_in_w = (const float*)d_in[11];
    const float* m_cw   = (const float*)d_in[12];
    const float* m_cb   = (const float*)d_in[13];
    const float* m_xp   = (const float*)d_in[14];
    const float* m_dtw  = (const float*)d_in[15];
    const float* m_dtb  = (const float*)d_in[16];
    const float* m_Alog = (const float*)d_in[17];
    const float* m_D    = (const float*)d_in[18];
    const float* m_outw = (const float*)d_in[19];
    const float* se_w1  = (const float*)d_in[20];
    const float* se_b1  = (const float*)d_in[21];
    const float* se_w2  = (const float*)d_in[22];
    const float* se_b2  = (const float*)d_in[23];
    const float* mlp_w1 = (const float*)d_in[24];
    const float* mlp_b1 = (const float*)d_in[25];
    const float* mlp_w2 = (const float*)d_in[26];
    const float* mlp_b2 = (const float*)d_in[27];
    const float* gamma1 = (const float*)d_in[28];
    const float* gamma2 = (const float*)d_in[29];
    float* out = (float*)d_out;

    static int attn_smem = 4*(NTOK*65) + 64*65 + NTOK*52 + NTOK;   // floats
    int attn_bytes = attn_smem * 4;
    int xdbl_bytes = KDIR*CX*DI_*4;
    cudaFuncSetAttribute(attn_kernel, cudaFuncAttributeMaxDynamicSharedMemorySize, attn_bytes);
    cudaFuncSetAttribute(xdbl_kernel, cudaFuncAttributeMaxDynamicSharedMemorySize, xdbl_bytes);

    // attention branch -> g_y[:, 0:64]
    attn_kernel<<<1024, 256, attn_bytes>>>(x, wq, wk, wv, wproj, bproj, gq, gk, gv);

    // mamba branch
    rmsinproj_kernel<<<196, 256>>>(x, m_in_w, gvm);
    dwconv_kernel<<<25088, 256>>>(m_cw, m_cb);
    xdbl_kernel<<<196, 256, xdbl_bytes>>>(m_xp);
    scan_kernel<<<128, 128>>>(m_dtw, m_dtb, m_Alog, m_D);
    merge_kernel<<<196, 256>>>(m_outw);

    // SE + residual 1
    pool_kernel<<<BB*DIMC, 256>>>();
    se_kernel<<<1, 128>>>(se_w1, se_b1, se_w2, se_b2);
    resid1_kernel<<<25088, 256>>>(x, gamma1);

    // MLP + residual 2
    mlp1_kernel<<<196, 256>>>(gmlp, mlp_w1, mlp_b1);
    mlp2_kernel<<<196, 256>>>(mlp_w2, mlp_b2, gamma2, out);
}

// round 4
// speedup vs baseline: 1.4328x; 1.4328x over previous
#include <cuda_runtime.h>
#include <cuda_bf16.h>
#include <math.h>

// ---------------- constants ----------------
#define BBATCH 16
#define DIMC  128
#define HDC   64
#define LLC   3136      // 56*56
#define NTOK  49
#define NHEAD 8
#define DI_   128
#define DST_  16
#define KDIR  4
#define CX    36        // DTR + 2*DST
#define HID4  512

// ---------------- scratch (static device memory; no allocations) ----------------
__device__ float g_xn64[(size_t)BBATCH*HDC*LLC];       // rms-normed x2 (gvm folded)
__device__ float g_tmp [(size_t)BBATCH*DI_*LLC];       // mamba in-proj output
__device__ float g_xm  [(size_t)BBATCH*DI_*LLC];       // after dwconv+silu
__device__ float g_pj  [(size_t)BBATCH*KDIR*CX*LLC];   // x_dbl proj, natural pixel order
__device__ float g_ys  [(size_t)BBATCH*KDIR*DI_*LLC];  // scan outputs per direction
__device__ float g_ymg [(size_t)BBATCH*DI_*LLC];       // merged + gelu
__device__ float g_y   [(size_t)BBATCH*DIMC*LLC];      // concat(y_attn, y_mamba)
__device__ float g_pool[BBATCH*DIMC];
__device__ float g_sse [BBATCH*DIMC];
__device__ float g_xr  [(size_t)BBATCH*DIMC*LLC];      // x + gamma1 * y * s
__device__ __nv_bfloat16 g_xnbf[(size_t)BBATCH*DIMC*LLC]; // rms-normed (gmlp folded), bf16
__device__ __nv_bfloat16 g_h   [(size_t)BBATCH*HID4*LLC]; // MLP hidden, bf16
__device__ __nv_bfloat16 g_w1bf[HID4*DIMC];
__device__ __nv_bfloat16 g_w2bf[DIMC*HID4];
__device__ float g_wx[KDIR*CX*DI_];                    // transposed xproj [144][128]

// ---------------- helpers ----------------
__device__ __forceinline__ float fgelu(float x){
    float u = 0.7978845608028654f*(x + 0.044715f*x*x*x);
    float t;
    asm("tanh.approx.f32 %0, %1;" : "=f"(t) : "f"(u));
    return 0.5f*x*(1.f+t);
}
__device__ __forceinline__ float fsilu(float x){
    return x * (1.f/(1.f+__expf(-x)));
}

// ---------------- 0. weight prep ----------------
__global__ void wprep_kernel(const float* __restrict__ w1, const float* __restrict__ w2,
                             const float* __restrict__ xp)
{
    int i = blockIdx.x*256 + threadIdx.x;
    if (i < HID4*DIMC) g_w1bf[i] = __float2bfloat16(w1[i]);
    if (i < DIMC*HID4) g_w2bf[i] = __float2bfloat16(w2[i]);
    if (i < KDIR*CX*DI_){
        int o = i >> 7, d = i & 127;
        int k = o / CX, c = o - k*CX;
        g_wx[i] = xp[(k*DI_ + d)*CX + c];
    }
}

// ---------------- 1. window attention (unchanged from passing R2) ----------------
__global__ void attn_kernel(const float* __restrict__ x,
    const float* __restrict__ wq, const float* __restrict__ wk, const float* __restrict__ wv,
    const float* __restrict__ wproj, const float* __restrict__ bproj,
    const float* __restrict__ gq, const float* __restrict__ gk, const float* __restrict__ gv)
{
    extern __shared__ float sm[];
    float* xw  = sm;
    float* qs  = xw + NTOK*65;
    float* ks  = qs + NTOK*65;
    float* vs  = ks + NTOK*65;
    float* ws  = vs + NTOK*65;
    float* sc  = ws + 64*65;
    float* inv = sc + NTOK*52;

    int tid = threadIdx.x;
    int bw  = blockIdx.x;
    int b   = bw >> 6;
    int wh  = (bw >> 3) & 7;
    int wwi = bw & 7;
    int h0  = wh*7, w0 = wwi*7;
    const float* xb = x + (size_t)b*DIMC*LLC;

    for (int i = tid; i < NTOK*64; i += blockDim.x){
        int c = i / NTOK, t = i - c*NTOK;
        int hh = h0 + t/7, ww2 = w0 + t%7;
        xw[t*65 + c] = xb[(size_t)c*LLC + hh*56 + ww2];
    }
    __syncthreads();
    if (tid < NTOK){
        float ssum = 0.f;
        #pragma unroll
        for (int c = 0; c < 64; c++){ float v = xw[tid*65+c]; ssum += v*v; }
        inv[tid] = rsqrtf(ssum*(1.f/64.f) + 1e-5f);
    }
    __syncthreads();

    for (int pj = 0; pj < 3; pj++){
        const float* W = (pj==0) ? wq : ((pj==1) ? wk : wv);
        const float* G = (pj==0) ? gq : ((pj==1) ? gk : gv);
        float* OUT     = (pj==0) ? qs : ((pj==1) ? ks : vs);
        for (int i = tid; i < 64*64; i += blockDim.x){
            int o = i >> 6, d2 = i & 63;
            ws[o*65 + d2] = W[o*64 + d2] * G[d2];
        }
        __syncthreads();
        for (int idx = tid; idx < NTOK*64; idx += blockDim.x){
            int i2 = idx >> 6, o = idx & 63;
            float acc = 0.f;
            #pragma unroll
            for (int d2 = 0; d2 < 64; d2++)
                acc = fmaf(xw[i2*65+d2], ws[o*65+d2], acc);
            OUT[i2*65 + o] = acc * inv[i2];
        }
        __syncthreads();
    }

    float* ob = xw;
    for (int hh2 = 0; hh2 < NHEAD; hh2++){
        int hb = hh2*8;
        for (int idx = tid; idx < NTOK*NTOK; idx += blockDim.x){
            int i2 = idx / NTOK, j = idx - i2*NTOK;
            float acc = 0.f;
            #pragma unroll
            for (int dd = 0; dd < 8; dd++)
                acc = fmaf(qs[i2*65+hb+dd], ks[j*65+hb+dd], acc);
            sc[i2*52 + j] = acc * 0.35355339059327373f;
        }
        __syncthreads();
        if (tid < NTOK){
            float m = -1e30f;
            for (int j = 0; j < NTOK; j++) m = fmaxf(m, sc[tid*52+j]);
            float s = 0.f;
            for (int j = 0; j < NTOK; j++){ float e = __expf(sc[tid*52+j]-m); sc[tid*52+j] = e; s += e; }
            float r = 1.f/s;
            for (int j = 0; j < NTOK; j++) sc[tid*52+j] *= r;
        }
        __syncthreads();
        for (int idx = tid; idx < NTOK*8; idx += blockDim.x){
            int i2 = idx >> 3, dd = idx & 7;
            float acc = 0.f;
            for (int j = 0; j < NTOK; j++)
                acc = fmaf(sc[i2*52+j], vs[j*65+hb+dd], acc);
            ob[i2*65 + hb + dd] = acc;
        }
        __syncthreads();
    }

    for (int i = tid; i < 64*64; i += blockDim.x){
        int o = i >> 6, d2 = i & 63;
        ws[o*65 + d2] = wproj[o*64 + d2];
    }
    __syncthreads();
    for (int idx = tid; idx < NTOK*64; idx += blockDim.x){
        int o = idx / NTOK, i2 = idx - o*NTOK;
        float acc = bproj[o];
        #pragma unroll
        for (int d2 = 0; d2 < 64; d2++)
            acc = fmaf(ob[i2*65+d2], ws[o*65+d2], acc);
        int hh = h0 + i2/7, wcol = w0 + i2%7;
        g_y[((size_t)b*DIMC + o)*LLC + hh*56 + wcol] = acc;
    }
}

// ---------------- 2. rms2d over x2 (gvm folded) ----------------
__global__ void rmsA_kernel(const float* __restrict__ x, const float* __restrict__ gvm)
{
    int gid = blockIdx.x*256 + threadIdx.x;
    int b = gid / LLC, p = gid - b*LLC;
    const float* xb = x + ((size_t)b*DIMC + HDC)*LLC + p;
    float xr[64];
    float s = 0.f;
    #pragma unroll
    for (int c = 0; c < 64; c++){ float v = xb[(size_t)c*LLC]; xr[c] = v; s += v*v; }
    float inv = rsqrtf(s*(1.f/64.f) + 1e-5f);
    float* ob = g_xn64 + (size_t)b*HDC*LLC + p;
    #pragma unroll
    for (int c = 0; c < 64; c++) ob[(size_t)c*LLC] = xr[c]*inv*gvm[c];
}

// ---------------- generic fp32 tiled GEMM: OUT[o,p] = sum_k W[o,k] X[k,p] ----------------
// grid (25 ptiles, 16 batches), 256 threads; each thread: 4 pixels x M/8 outs
template<int M, int K, int OS>
__global__ __launch_bounds__(256) void gemm_f32_kernel(
    const float* __restrict__ W, const float* __restrict__ X,
    float* __restrict__ OUT, int o_off)
{
    __shared__ float Xs[16*132];
    __shared__ float Ws[M*16];
    int tid = threadIdx.x, tx = tid & 31, ty = tid >> 5;
    int p0 = blockIdx.x*128;
    int b  = blockIdx.y;
    constexpr int MO = M/8;
    float acc[MO][4];
    #pragma unroll
    for (int j = 0; j < MO; j++){ acc[j][0]=0.f; acc[j][1]=0.f; acc[j][2]=0.f; acc[j][3]=0.f; }
    const float* xb = X + (size_t)b*K*LLC;
    for (int k0 = 0; k0 < K; k0 += 16){
        __syncthreads();
        for (int i = tid; i < 16*128; i += 256){
            int kk = i >> 7, px = i & 127;
            float v = 0.f;
            if (p0 + px < LLC) v = xb[(size_t)(k0+kk)*LLC + p0 + px];
            Xs[kk*132 + px] = v;
        }
        for (int i = tid; i < M*16; i += 256){
            int o = i >> 4, kk = i & 15;
            Ws[i] = W[(size_t)o*K + k0 + kk];
        }
        __syncthreads();
        #pragma unroll
        for (int kk = 0; kk < 16; kk++){
            float4 xv = *(const float4*)&Xs[kk*132 + tx*4];
            #pragma unroll
            for (int j = 0; j < MO; j++){
                float w = Ws[(j*8 + ty)*16 + kk];
                acc[j][0] = fmaf(xv.x, w, acc[j][0]);
                acc[j][1] = fmaf(xv.y, w, acc[j][1]);
                acc[j][2] = fmaf(xv.z, w, acc[j][2]);
                acc[j][3] = fmaf(xv.w, w, acc[j][3]);
            }
        }
    }
    int p = p0 + tx*4;
    if (p < LLC){
        #pragma unroll
        for (int j = 0; j < MO; j++){
            int o = j*8 + ty;
            *(float4*)&OUT[((size_t)b*OS + o_off + o)*LLC + p] =
                make_float4(acc[j][0], acc[j][1], acc[j][2], acc[j][3]);
        }
    }
}

// ---------------- 3. depthwise 3x3 + bias + silu ----------------
__global__ void dwconv_kernel(const float* __restrict__ cw, const float* __restrict__ cb)
{
    int gid = blockIdx.x*blockDim.x + threadIdx.x;
    int p  = gid % LLC;
    int bc = gid / LLC;
    int c  = bc % DI_;
    int h = p / 56, w = p - h*56;
    const float* xp = g_tmp + (size_t)bc*LLC;
    const float* wc = cw + c*9;
    float acc = cb[c];
    #pragma unroll
    for (int ky = 0; ky < 3; ky++){
        int hy = h + ky - 1;
        if (hy < 0 || hy >= 56) continue;
        #pragma unroll
        for (int kx = 0; kx < 3; kx++){
            int wx = w + kx - 1;
            if (wx < 0 || wx >= 56) continue;
            acc = fmaf(xp[hy*56 + wx], wc[ky*3+kx], acc);
        }
    }
    g_xm[gid] = fsilu(acc);
}

// ---------------- 4. selective scan (4 threads/channel, exp factorization) ----------------
__global__ __launch_bounds__(256) void scan_kernel(const float* __restrict__ dtw,
    const float* __restrict__ dtb, const float* __restrict__ alog, const float* __restrict__ Dp)
{
    __shared__ float Uc[64*65];
    __shared__ float Pc[64*44];
    __shared__ float Yc[64*65];
    __shared__ int   pqs[64];
    int tid  = threadIdx.x;
    int blk  = blockIdx.x;
    int half = blk & 1;
    int bk   = blk >> 1;
    int k    = bk & 3;
    int b    = bk >> 2;
    int ch   = tid >> 2;
    int sub  = tid & 3;
    int ng   = sub*4;
    int d    = half*64 + ch;
    int kd   = k*DI_ + d;

    float dtw4[4];
    #pragma unroll
    for (int r = 0; r < 4; r++) dtw4[r] = dtw[kd*4 + r];
    float dtbv = dtb[kd];
    float Dd   = Dp[kd];
    float A2[4];
    bool structured = true;
    #pragma unroll
    for (int n = 0; n < 4; n++){
        A2[n] = -__expf(alog[kd*DST_ + ng + n]);
        if (fabsf(A2[n] + (float)(ng + n + 1)) > 1e-3f) structured = false;
    }
    float hst[4] = {0.f, 0.f, 0.f, 0.f};

    const float* xmb = g_xm + ((size_t)b*DI_ + half*64)*LLC;
    const float* pdb = g_pj + ((size_t)(b*KDIR + k))*CX*LLC;
    float* yb = g_ys + (((size_t)(b*KDIR + k))*DI_ + half*64)*LLC;

    for (int s0 = 0; s0 < LLC; s0 += 64){
        if (tid < 64){
            int s = s0 + tid;
            int pq;
            if (k == 0)      pq = s;
            else if (k == 1) pq = (s % 56)*56 + s/56;
            else if (k == 2) pq = LLC-1-s;
            else { int s2 = LLC-1-s; pq = (s2 % 56)*56 + s2/56; }
            pqs[tid] = pq;
        }
        __syncthreads();
        for (int i = tid; i < 64*64; i += 256){
            int dd = i >> 6, t = i & 63;
            Uc[dd*65 + t] = xmb[(size_t)dd*LLC + pqs[t]];
        }
        for (int i = tid; i < CX*64; i += 256){
            int c = i >> 6, t = i & 63;
            Pc[t*44 + c] = pdb[(size_t)c*LLC + pqs[t]];
        }
        __syncthreads();
        for (int t = 0; t < 64; t++){
            const float* Pt = &Pc[t*44];
            float4 dtv = *(const float4*)Pt;
            float dtr = dtbv;
            dtr = fmaf(dtv.x, dtw4[0], dtr);
            dtr = fmaf(dtv.y, dtw4[1], dtr);
            dtr = fmaf(dtv.z, dtw4[2], dtr);
            dtr = fmaf(dtv.w, dtw4[3], dtr);
            float e = __expf(dtr);
            float delta = (dtr > 20.f) ? dtr : __logf(1.f + e);
            float u  = Uc[ch*65 + t];
            float du = delta*u;
            float4 Bv = *(const float4*)(Pt + 4 + ng);
            float4 Cv = *(const float4*)(Pt + 20 + ng);
            float pe0, pe1, pe2, pe3;
            if (structured){
                float p1 = __expf(-delta);
                float p2 = p1*p1, p4 = p2*p2, p8 = p4*p4;
                float q = (sub==0) ? p1 : (sub==1) ? p4*p1 : (sub==2) ? p8*p1 : p8*p4*p1;
                pe0 = q; pe1 = pe0*p1; pe2 = pe1*p1; pe3 = pe2*p1;
            } else {
                pe0 = __expf(delta*A2[0]); pe1 = __expf(delta*A2[1]);
                pe2 = __expf(delta*A2[2]); pe3 = __expf(delta*A2[3]);
            }
            hst[0] = fmaf(pe0, hst[0], du*Bv.x);
            hst[1] = fmaf(pe1, hst[1], du*Bv.y);
            hst[2] = fmaf(pe2, hst[2], du*Bv.z);
            hst[3] = fmaf(pe3, hst[3], du*Bv.w);
            float y = hst[0]*Cv.x;
            y = fmaf(hst[1], Cv.y, y);
            y = fmaf(hst[2], Cv.z, y);
            y = fmaf(hst[3], Cv.w, y);
            y += __shfl_xor_sync(0xffffffffu, y, 1);
            y += __shfl_xor_sync(0xffffffffu, y, 2);
            if (sub == 0) Yc[ch*65 + t] = fmaf(u, Dd, y);
        }
        __syncthreads();
        for (int i = tid; i < 64*64; i += 256){
            int dd = i >> 6, t = i & 63;
            yb[(size_t)dd*LLC + s0 + t] = Yc[dd*65 + t];
        }
        __syncthreads();
    }
}

// ---------------- 5. cross_merge + gelu (smem transpose, no sector blowup) ----------------
// grid (128 channels, 16 batches), 256 threads
__global__ void mergegelu_kernel(void)
{
    __shared__ float sm1[56*57 + 8];
    __shared__ float sm3[56*57 + 8];
    int tid = threadIdx.x;
    int dch = blockIdx.x;
    int b   = blockIdx.y;
    const float* y0p = g_ys + (((size_t)(b*KDIR + 0))*DI_ + dch)*LLC;
    const float* y1p = g_ys + (((size_t)(b*KDIR + 1))*DI_ + dch)*LLC;
    const float* y2p = g_ys + (((size_t)(b*KDIR + 2))*DI_ + dch)*LLC;
    const float* y3p = g_ys + (((size_t)(b*KDIR + 3))*DI_ + dch)*LLC;
    for (int i = tid; i < LLC; i += 256){
        int hh = i / 56, ww = i - hh*56;
        sm1[hh*57 + ww] = y1p[i];
        sm3[hh*57 + ww] = y3p[i];
    }
    __syncthreads();
    float* op = g_ymg + ((size_t)b*DI_ + dch)*LLC;
    for (int p = tid; p < LLC; p += 256){
        int hh = p / 56, ww = p - hh*56;
        float v = y0p[p] + y2p[LLC-1-p] + sm1[ww*57 + hh] + sm3[(55-ww)*57 + (55-hh)];
        op[p] = fgelu(v);
    }
}

// ---------------- 6. pool / SE / residual1 ----------------
__global__ void pool_kernel(void)
{
    __shared__ float red[256];
    int bc = blockIdx.x;
    const float* yb = g_y + (size_t)bc*LLC;
    float s = 0.f;
    for (int i = threadIdx.x; i < LLC; i += 256) s += yb[i];
    red[threadIdx.x] = s;
    __syncthreads();
    for (int st = 128; st > 0; st >>= 1){
        if (threadIdx.x < st) red[threadIdx.x] += red[threadIdx.x + st];
        __syncthreads();
    }
    if (threadIdx.x == 0) g_pool[bc] = red[0]*(1.f/LLC);
}

__global__ void se_kernel(const float* __restrict__ w1, const float* __restrict__ b1,
    const float* __restrict__ w2, const float* __restrict__ b2)
{
    __shared__ float pv[DIMC];
    __shared__ float h1[32];
    int tid = threadIdx.x;
    for (int b = 0; b < BBATCH; b++){
        if (tid < DIMC) pv[tid] = g_pool[b*DIMC + tid];
        __syncthreads();
        if (tid < 32){
            float acc = b1[tid];
            #pragma unroll
            for (int c = 0; c < DIMC; c++) acc = fmaf(pv[c], w1[tid*DIMC + c], acc);
            h1[tid] = fmaxf(acc, 0.f);
        }
        __syncthreads();
        if (tid < DIMC){
            float acc = b2[tid];
            #pragma unroll
            for (int j = 0; j < 32; j++) acc = fmaf(h1[j], w2[tid*32 + j], acc);
            g_sse[b*DIMC + tid] = 1.f/(1.f + __expf(-acc));
        }
        __syncthreads();
    }
}

__global__ void resid1_kernel(const float* __restrict__ x, const float* __restrict__ gamma1)
{
    int gid = blockIdx.x*blockDim.x + threadIdx.x;
    int bc = gid / LLC;
    int c = bc % DIMC;
    g_xr[gid] = fmaf(gamma1[c]*g_sse[bc], g_y[gid], x[gid]);
}

// ---------------- 7. rms2d before MLP -> bf16 (gmlp folded) ----------------
__global__ void rmsB_kernel(const float* __restrict__ gmlp)
{
    int gid = blockIdx.x*256 + threadIdx.x;
    int b = gid / LLC, p = gid - b*LLC;
    const float* xb = g_xr + (size_t)b*DIMC*LLC + p;
    float s = 0.f;
    for (int c = 0; c < DIMC; c++){ float v = xb[(size_t)c*LLC]; s += v*v; }
    float inv = rsqrtf(s*(1.f/DIMC) + 1e-5f);
    __nv_bfloat16* ob = g_xnbf + (size_t)b*DIMC*LLC + p;
    for (int c = 0; c < DIMC; c++)
        ob[(size_t)c*LLC] = __float2bfloat16(xb[(size_t)c*LLC]*inv*gmlp[c]);
}

// ---------------- 8. bf16 tensor-core GEMM for MLP ----------------
// MODE 1: h = gelu(W1 @ xn + b1), MT=512,K=128 -> g_h (bf16)
// MODE 2: out = xr + gamma2*(W2 @ h + b2),  MT=128,K=512 -> outf (fp32)
// BM=128 BN=128 BK=32, 8 warps (2x4), warp tile 64x32
template<int MODE>
__global__ __launch_bounds__(256) void mma_mlp_kernel(
    const float* __restrict__ bias, const float* __restrict__ gamma2, float* __restrict__ outf)
{
    constexpr int MT = (MODE == 1) ? HID4 : DIMC;
    constexpr int K  = (MODE == 1) ? DIMC : HID4;
    __shared__ __nv_bfloat16 As[128*40];    // [m][k], stride 40
    __shared__ __nv_bfloat16 Bs[32*136];    // [k][p], stride 136
    int tid = threadIdx.x;
    int lane = tid & 31, wid = tid >> 5;
    int wm = wid >> 2, wn = wid & 3;
    int p0 = blockIdx.x*128;
    int m0 = blockIdx.y*128;
    int bz = blockIdx.z;
    const __nv_bfloat16* W = (MODE == 1) ? g_w1bf : g_w2bf;
    const __nv_bfloat16* X = (MODE == 1) ? g_xnbf : g_h;

    float acc[4][4][4];
    #pragma unroll
    for (int i = 0; i < 4; i++)
        #pragma unroll
        for (int j = 0; j < 4; j++)
            #pragma unroll
            for (int q = 0; q < 4; q++) acc[i][j][q] = 0.f;

    for (int kc = 0; kc < K; kc += 32){
        __syncthreads();
        {   // A tile: 128 rows x 32 k (bf16), 2 x uint4 per thread
            int i0 = tid*2;
            #pragma unroll
            for (int r = 0; r < 2; r++){
                int ii = i0 + r;
                int row = ii >> 2, seg = ii & 3;
                uint4 v = *(const uint4*)(W + (size_t)(m0 + row)*K + kc + seg*8);
                *(uint4*)(&As[row*40 + seg*8]) = v;
            }
        }
        {   // B tile: 32 k x 128 pixels
            int kk = tid >> 3, pg = tid & 7;
            const __nv_bfloat16* src = X + ((size_t)bz*K + kc + kk)*LLC + p0 + pg*16;
            #pragma unroll
            for (int r = 0; r < 2; r++){
                int p = p0 + pg*16 + r*8;
                uint4 v = make_uint4(0u,0u,0u,0u);
                if (p < LLC) v = *(const uint4*)(src + r*8);
                *(uint4*)(&Bs[kk*136 + pg*16 + r*8]) = v;
            }
        }
        __syncthreads();
        #pragma unroll
        for (int ks = 0; ks < 2; ks++){
            int kk16 = ks*16;
            unsigned a[4][4], bfr[4][2];
            const unsigned* As32 = (const unsigned*)As;
            #pragma unroll
            for (int fm = 0; fm < 4; fm++){
                int row = wm*64 + fm*16 + (lane >> 2);
                int c = (kk16 >> 1) + (lane & 3);
                a[fm][0] = As32[row*20 + c];
                a[fm][1] = As32[(row+8)*20 + c];
                a[fm][2] = As32[row*20 + c + 4];
                a[fm][3] = As32[(row+8)*20 + c + 4];
            }
            const unsigned short* Bu = (const unsigned short*)Bs;
            #pragma unroll
            for (int fn = 0; fn < 4; fn++){
                int col = wn*32 + fn*8 + (lane >> 2);
                int kb = kk16 + (lane & 3)*2;
                unsigned lo0 = Bu[kb*136 + col],     hi0 = Bu[(kb+1)*136 + col];
                unsigned lo1 = Bu[(kb+8)*136 + col], hi1 = Bu[(kb+9)*136 + col];
                bfr[fn][0] = lo0 | (hi0 << 16);
                bfr[fn][1] = lo1 | (hi1 << 16);
            }
            #pragma unroll
            for (int fm = 0; fm < 4; fm++)
                #pragma unroll
                for (int fn = 0; fn < 4; fn++){
                    asm volatile(
                        "mma.sync.aligned.m16n8k16.row.col.f32.bf16.bf16.f32 "
                        "{%0,%1,%2,%3}, {%4,%5,%6,%7}, {%8,%9}, {%0,%1,%2,%3};"
                        : "+f"(acc[fm][fn][0]), "+f"(acc[fm][fn][1]),
                          "+f"(acc[fm][fn][2]), "+f"(acc[fm][fn][3])
                        : "r"(a[fm][0]), "r"(a[fm][1]), "r"(a[fm][2]), "r"(a[fm][3]),
                          "r"(bfr[fn][0]), "r"(bfr[fn][1]));
                }
        }
    }

    // epilogue
    int r = lane >> 2, c2 = (lane & 3)*2;
    #pragma unroll
    for (int fm = 0; fm < 4; fm++){
        int m = m0 + wm*64 + fm*16 + r;
        float bv0 = bias[m], bv1 = bias[m+8];
        #pragma unroll
        for (int fn = 0; fn < 4; fn++){
            int p = p0 + wn*32 + fn*8 + c2;
            if (p < LLC){
                if (MODE == 1){
                    __nv_bfloat162 h2;
                    h2.x = __float2bfloat16(fgelu(acc[fm][fn][0] + bv0));
                    h2.y = __float2bfloat16(fgelu(acc[fm][fn][1] + bv0));
                    *(__nv_bfloat162*)&g_h[((size_t)bz*HID4 + m)*LLC + p] = h2;
                    __nv_bfloat162 h3;
                    h3.x = __float2bfloat16(fgelu(acc[fm][fn][2] + bv1));
                    h3.y = __float2bfloat16(fgelu(acc[fm][fn][3] + bv1));
                    *(__nv_bfloat162*)&g_h[((size_t)bz*HID4 + m + 8)*LLC + p] = h3;
                } else {
                    float g0 = gamma2[m], g1 = gamma2[m+8];
                    size_t o0 = ((size_t)bz*DIMC + m)*LLC + p;
                    size_t o1 = ((size_t)bz*DIMC + m + 8)*LLC + p;
                    float2 xr0 = *(const float2*)&g_xr[o0];
                    float2 xr1 = *(const float2*)&g_xr[o1];
                    float2 ov0, ov1;
                    ov0.x = fmaf(g0, acc[fm][fn][0] + bv0, xr0.x);
                    ov0.y = fmaf(g0, acc[fm][fn][1] + bv0, xr0.y);
                    ov1.x = fmaf(g1, acc[fm][fn][2] + bv1, xr1.x);
                    ov1.y = fmaf(g1, acc[fm][fn][3] + bv1, xr1.y);
                    *(float2*)&outf[o0] = ov0;
                    *(float2*)&outf[o1] = ov1;
                }
            }
        }
    }
}

// ---------------- launch ----------------
extern "C" void kernel_launch(void* const* d_in, const int* in_sizes, int n_in,
                              void* d_out, int out_size)
{
    const float* x      = (const float*)d_in[0];
    const float* wq     = (const float*)d_in[1];
    const float* wk     = (const float*)d_in[2];
    const float* wv     = (const float*)d_in[3];
    const float* wproj  = (const float*)d_in[4];
    const float* bproj  = (const float*)d_in[5];
    const float* gq     = (const float*)d_in[6];
    const float* gk     = (const float*)d_in[7];
    const float* gv     = (const float*)d_in[8];
    const float* gvm    = (const float*)d_in[9];
    const float* gmlp   = (const float*)d_in[10];
    const float* m_in_w = (const float*)d_in[11];
    const float* m_cw   = (const float*)d_in[12];
    const float* m_cb   = (const float*)d_in[13];
    const float* m_xp   = (const float*)d_in[14];
    const float* m_dtw  = (const float*)d_in[15];
    const float* m_dtb  = (const float*)d_in[16];
    const float* m_Alog = (const float*)d_in[17];
    const float* m_D    = (const float*)d_in[18];
    const float* m_outw = (const float*)d_in[19];
    const float* se_w1  = (const float*)d_in[20];
    const float* se_b1  = (const float*)d_in[21];
    const float* se_w2  = (const float*)d_in[22];
    const float* se_b2  = (const float*)d_in[23];
    const float* mlp_w1 = (const float*)d_in[24];
    const float* mlp_b1 = (const float*)d_in[25];
    const float* mlp_w2 = (const float*)d_in[26];
    const float* mlp_b2 = (const float*)d_in[27];
    const float* gamma1 = (const float*)d_in[28];
    const float* gamma2 = (const float*)d_in[29];
    float* out = (float*)d_out;

    void *p_xn64, *p_tmp, *p_xm, *p_pj, *p_ymg, *p_y, *p_wx;
    cudaGetSymbolAddress(&p_xn64, g_xn64);
    cudaGetSymbolAddress(&p_tmp,  g_tmp);
    cudaGetSymbolAddress(&p_xm,   g_xm);
    cudaGetSymbolAddress(&p_pj,   g_pj);
    cudaGetSymbolAddress(&p_ymg,  g_ymg);
    cudaGetSymbolAddress(&p_y,    g_y);
    cudaGetSymbolAddress(&p_wx,   g_wx);

    int attn_bytes = (4*(NTOK*65) + 64*65 + NTOK*52 + NTOK)*4;
    cudaFuncSetAttribute(attn_kernel, cudaFuncAttributeMaxDynamicSharedMemorySize, attn_bytes);

    wprep_kernel<<<256, 256>>>(mlp_w1, mlp_w2, m_xp);
    attn_kernel<<<1024, 256, attn_bytes>>>(x, wq, wk, wv, wproj, bproj, gq, gk, gv);

    // mamba branch
    rmsA_kernel<<<196, 256>>>(x, gvm);
    gemm_f32_kernel<128, 64, 128><<<dim3(25, 16), 256>>>(m_in_w, (const float*)p_xn64, (float*)p_tmp, 0);
    dwconv_kernel<<<25088, 256>>>(m_cw, m_cb);
    gemm_f32_kernel<144, 128, 144><<<dim3(25, 16), 256>>>((const float*)p_wx, (const float*)p_xm, (float*)p_pj, 0);
    scan_kernel<<<128, 256>>>(m_dtw, m_dtb, m_Alog, m_D);
    mergegelu_kernel<<<dim3(128, 16), 256>>>();
    gemm_f32_kernel<64, 128, 128><<<dim3(25, 16), 256>>>(m_outw, (const float*)p_ymg, (float*)p_y, 64);

    // SE + residual 1
    pool_kernel<<<BBATCH*DIMC, 256>>>();
    se_kernel<<<1, 128>>>(se_w1, se_b1, se_w2, se_b2);
    resid1_kernel<<<25088, 256>>>(x, gamma1);

    // MLP (bf16 tensor cores) + residual 2
    rmsB_kernel<<<196, 256>>>(gmlp);
    mma_mlp_kernel<1><<<dim3(25, 4, 16), 256>>>(mlp_b1, nullptr, nullptr);
    mma_mlp_kernel<2><<<dim3(25, 1, 16), 256>>>(mlp_b2, gamma2, out);
}

// round 5
// speedup vs baseline: 2.3983x; 1.6738x over previous
#include <cuda_runtime.h>
#include <cuda_bf16.h>
#include <math.h>

// ---------------- constants ----------------
#define BBATCH 16
#define DIMC  128
#define HDC   64
#define LLC   3136      // 56*56
#define NTOK  49
#define DI_   128
#define DST_  16
#define KDIR  4
#define CX    36
#define HID4  512

// ---------------- scratch ----------------
__device__ float g_xn1 [(size_t)BBATCH*HDC*LLC];       // rms-normed x1 (no gain)
__device__ float g_xn64[(size_t)BBATCH*HDC*LLC];       // rms-normed x2 (gvm folded)
__device__ float g_qkv [(size_t)BBATCH*192*LLC];       // q/k/v per pixel
__device__ float g_attno[(size_t)BBATCH*HDC*LLC];      // attention out (pre-proj)
__device__ float g_tmp [(size_t)BBATCH*DI_*LLC];       // mamba in-proj output
__device__ float g_xm  [(size_t)BBATCH*DI_*LLC];       // after dwconv+silu
__device__ float g_xmT [(size_t)BBATCH*DI_*LLC];       // transposed copy
__device__ float g_pj  [(size_t)BBATCH*KDIR*CX*LLC];   // x_dbl proj, natural order
__device__ float g_pjT [(size_t)BBATCH*2*CX*LLC];      // transposed k1 (slot0), k3 (slot1)
__device__ float g_ys  [(size_t)BBATCH*KDIR*DI_*LLC];  // scan outputs (scan order)
__device__ float g_ymg [(size_t)BBATCH*DI_*LLC];       // merged + gelu
__device__ float g_y   [(size_t)BBATCH*DIMC*LLC];      // concat(y_attn, y_mamba)
__device__ float g_pool[BBATCH*DIMC];
__device__ float g_sse [BBATCH*DIMC];
__device__ float g_xr  [(size_t)BBATCH*DIMC*LLC];
__device__ __nv_bfloat16 g_xnbf[(size_t)BBATCH*DIMC*LLC];
__device__ __nv_bfloat16 g_h   [(size_t)BBATCH*HID4*LLC];
__device__ __nv_bfloat16 g_w1bf[HID4*DIMC];
__device__ __nv_bfloat16 g_w2bf[DIMC*HID4];
__device__ float g_wx  [KDIR*CX*DI_];                  // transposed xproj [144][128]
__device__ float g_wqkv[192*HDC];                      // gains folded

// ---------------- helpers ----------------
__device__ __forceinline__ float fgelu(float x){
    float u = 0.7978845608028654f*(x + 0.044715f*x*x*x);
    float t;
    asm("tanh.approx.f32 %0, %1;" : "=f"(t) : "f"(u));
    return 0.5f*x*(1.f+t);
}
__device__ __forceinline__ float fsilu(float x){
    return x * (1.f/(1.f+__expf(-x)));
}

// ---------------- 0. weight prep ----------------
__global__ void wprep_kernel(const float* __restrict__ w1, const float* __restrict__ w2,
    const float* __restrict__ xp,
    const float* __restrict__ wq, const float* __restrict__ wk, const float* __restrict__ wv,
    const float* __restrict__ gq, const float* __restrict__ gk, const float* __restrict__ gv)
{
    int i = blockIdx.x*256 + threadIdx.x;
    if (i < HID4*DIMC) g_w1bf[i] = __float2bfloat16(w1[i]);
    if (i < DIMC*HID4) g_w2bf[i] = __float2bfloat16(w2[i]);
    if (i < KDIR*CX*DI_){
        int o = i >> 7, d = i & 127;
        int k = o / CX, c = o - k*CX;
        g_wx[i] = xp[(k*DI_ + d)*CX + c];
    }
    if (i < 192*HDC){
        int o = i >> 6, c = i & 63;
        float v;
        if (o < 64)       v = wq[o*64 + c]*gq[c];
        else if (o < 128) v = wk[(o-64)*64 + c]*gk[c];
        else              v = wv[(o-128)*64 + c]*gv[c];
        g_wqkv[i] = v;
    }
}

// ---------------- 1. fused rms for both halves ----------------
// grid 784, block 256: tid = g*64 + px, g = channel group (32 ch), px = pixel
__global__ void rms1_kernel(const float* __restrict__ x, const float* __restrict__ gvm)
{
    __shared__ float ssum[256];
    int tid = threadIdx.x;
    int g = tid >> 6, px = tid & 63;
    int gp = blockIdx.x*64 + px;
    int b = gp / LLC, p = gp - b*LLC;
    const float* xb = x + ((size_t)b*DIMC + g*32)*LLC + p;
    float v[32];
    float s = 0.f;
    #pragma unroll
    for (int i = 0; i < 32; i++){ v[i] = xb[(size_t)i*LLC]; s += v[i]*v[i]; }
    ssum[tid] = s;
    __syncthreads();
    float tot = (g < 2) ? (ssum[px] + ssum[64+px]) : (ssum[128+px] + ssum[192+px]);
    float inv = rsqrtf(tot*(1.f/64.f) + 1e-5f);
    if (g < 2){
        float* ob = g_xn1 + ((size_t)b*HDC + g*32)*LLC + p;
        #pragma unroll
        for (int i = 0; i < 32; i++) ob[(size_t)i*LLC] = v[i]*inv;
    } else {
        int c0 = (g-2)*32;
        float* ob = g_xn64 + ((size_t)b*HDC + c0)*LLC + p;
        #pragma unroll
        for (int i = 0; i < 32; i++) ob[(size_t)i*LLC] = v[i]*inv*gvm[c0+i];
    }
}

// ---------------- generic fp32 tiled GEMM ----------------
// OUT[b][o_off+m0+o][p] = bias[o] + sum_k W[m0+o][k] X[b][k][p]
template<int MCH, int K>
__global__ __launch_bounds__(256, 3) void gemm_f32_kernel(
    const float* __restrict__ W, const float* __restrict__ X,
    float* __restrict__ OUT, const float* __restrict__ bias,
    int ostride, int o_off)
{
    __shared__ float Xs[16*132];
    __shared__ float Ws[MCH*16];
    int tid = threadIdx.x, tx = tid & 31, ty = tid >> 5;
    int p0 = blockIdx.x*128;
    int b  = blockIdx.y;
    int m0 = blockIdx.z*MCH;
    constexpr int MO = MCH/8;
    float acc[MO][4];
    #pragma unroll
    for (int j = 0; j < MO; j++){ acc[j][0]=0.f; acc[j][1]=0.f; acc[j][2]=0.f; acc[j][3]=0.f; }
    const float* xb = X + (size_t)b*K*LLC;
    for (int k0 = 0; k0 < K; k0 += 16){
        __syncthreads();
        #pragma unroll
        for (int r = 0; r < 8; r++){
            int i = tid + r*256;
            int kk = i >> 7, px = i & 127;
            float v = 0.f;
            if (p0 + px < LLC) v = xb[(size_t)(k0+kk)*LLC + p0 + px];
            Xs[kk*132 + px] = v;
        }
        for (int i = tid; i < MCH*16; i += 256){
            int o = i >> 4, kk = i & 15;
            Ws[i] = W[(size_t)(m0+o)*K + k0 + kk];
        }
        __syncthreads();
        #pragma unroll
        for (int kk = 0; kk < 16; kk++){
            float4 xv = *(const float4*)&Xs[kk*132 + tx*4];
            #pragma unroll
            for (int j = 0; j < MO; j++){
                float w = Ws[(j*8 + ty)*16 + kk];
                acc[j][0] = fmaf(xv.x, w, acc[j][0]);
                acc[j][1] = fmaf(xv.y, w, acc[j][1]);
                acc[j][2] = fmaf(xv.z, w, acc[j][2]);
                acc[j][3] = fmaf(xv.w, w, acc[j][3]);
            }
        }
    }
    int p = p0 + tx*4;
    if (p < LLC){
        #pragma unroll
        for (int j = 0; j < MO; j++){
            int o = m0 + j*8 + ty;
            float bv = bias ? bias[o] : 0.f;
            *(float4*)&OUT[((size_t)b*ostride + o_off + o)*LLC + p] =
                make_float4(acc[j][0]+bv, acc[j][1]+bv, acc[j][2]+bv, acc[j][3]+bv);
        }
    }
}

// ---------------- 2. window-attention core (warp per head, no block syncs) ----------------
__global__ void attncore_kernel(void)
{
    extern __shared__ float asm_[];
    float* q_s = asm_;                 // [8 heads][8 dd][52]
    float* k_s = q_s + 8*8*52;
    float* v_s = k_s + 8*8*52;
    float* s_s = v_s + 8*8*52;         // [8 heads][49][52]
    int tid = threadIdx.x, lane = tid & 31, h = tid >> 5;
    int bw = blockIdx.x;
    int b = bw >> 6, wh = (bw >> 3) & 7, wwi = bw & 7;
    int pbase = (wh*7)*56 + wwi*7;
    const float* qb = g_qkv + ((size_t)b*192 + h*8)*LLC;

    for (int it = lane; it < 392; it += 32){
        int dd = it / 49, j = it - dd*49;
        int pix = pbase + (j/7)*56 + j%7;
        q_s[(h*8+dd)*52 + j] = qb[(size_t)dd*LLC + pix];
        k_s[(h*8+dd)*52 + j] = qb[(size_t)(64+dd)*LLC + pix];
        v_s[(h*8+dd)*52 + j] = qb[(size_t)(128+dd)*LLC + pix];
    }
    for (int it = lane; it < 24; it += 32){
        int dd = it/3, jj = 49 + it%3;
        v_s[(h*8+dd)*52 + jj] = 0.f;
    }
    for (int it = lane; it < 147; it += 32){
        int r = it/3, jj = 49 + it%3;
        s_s[(h*49+r)*52 + jj] = 0.f;
    }
    __syncwarp();
    // scores
    for (int it = lane; it < 2401; it += 32){
        int r = it / 49, j = it - r*49;
        float acc = 0.f;
        #pragma unroll
        for (int dd = 0; dd < 8; dd++)
            acc = fmaf(q_s[(h*8+dd)*52 + r], k_s[(h*8+dd)*52 + j], acc);
        s_s[(h*49+r)*52 + j] = acc*0.35355339059327373f;
    }
    __syncwarp();
    // softmax per row
    for (int r = lane; r < 49; r += 32){
        float* row = &s_s[(h*49+r)*52];
        float m = -1e30f;
        for (int j = 0; j < 49; j++) m = fmaxf(m, row[j]);
        float s = 0.f;
        for (int j = 0; j < 49; j++){ float e = __expf(row[j]-m); row[j] = e; s += e; }
        float rinv = 1.f/s;
        for (int j = 0; j < 49; j++) row[j] *= rinv;
    }
    __syncwarp();
    // AV
    float* ob = g_attno + (size_t)b*HDC*LLC;
    for (int it = lane; it < 392; it += 32){
        int dd = it / 49, r = it - dd*49;
        float acc = 0.f;
        #pragma unroll
        for (int jq = 0; jq < 13; jq++){
            float4 sv = *(const float4*)&s_s[(h*49+r)*52 + jq*4];
            float4 vv = *(const float4*)&v_s[(h*8+dd)*52 + jq*4];
            acc = fmaf(sv.x, vv.x, acc);
            acc = fmaf(sv.y, vv.y, acc);
            acc = fmaf(sv.z, vv.z, acc);
            acc = fmaf(sv.w, vv.w, acc);
        }
        int pix = pbase + (r/7)*56 + r%7;
        ob[(size_t)(h*8+dd)*LLC + pix] = acc;
    }
}

// ---------------- 3. depthwise 3x3 + bias + silu ----------------
__global__ void dwconv_kernel(const float* __restrict__ cw, const float* __restrict__ cb)
{
    int gid = blockIdx.x*blockDim.x + threadIdx.x;
    int p  = gid % LLC;
    int bc = gid / LLC;
    int c  = bc % DI_;
    int h = p / 56, w = p - h*56;
    const float* xp = g_tmp + (size_t)bc*LLC;
    const float* wc = cw + c*9;
    float acc = cb[c];
    #pragma unroll
    for (int ky = 0; ky < 3; ky++){
        int hy = h + ky - 1;
        if (hy < 0 || hy >= 56) continue;
        #pragma unroll
        for (int kx = 0; kx < 3; kx++){
            int wx = w + kx - 1;
            if (wx < 0 || wx >= 56) continue;
            acc = fmaf(xp[hy*56 + wx], wc[ky*3+kx], acc);
        }
    }
    g_xm[gid] = fsilu(acc);
}

// ---------------- 4. transpose xm + pj(k1,k3): coalesced both ways ----------------
// grid 3200 blocks, 256 threads
__global__ void transpose_kernel(void)
{
    __shared__ float sm[56*57 + 8];
    int idx = blockIdx.x;
    const float* src;
    float* dst;
    if (idx < BBATCH*DI_){
        src = g_xm + (size_t)idx*LLC;
        dst = g_xmT + (size_t)idx*LLC;
    } else {
        int j = idx - BBATCH*DI_;
        int b = j / (2*CX), r = j - b*(2*CX);
        int kk = (r < CX) ? 1 : 3;
        int c = (r < CX) ? r : r - CX;
        src = g_pj + ((size_t)b*KDIR*CX + kk*CX + c)*LLC;
        dst = g_pjT + (size_t)j*LLC;
    }
    int tid = threadIdx.x;
    for (int i = tid; i < LLC; i += 256){
        int hh = i/56, ww = i - hh*56;
        sm[hh*57 + ww] = src[i];
    }
    __syncthreads();
    for (int i = tid; i < LLC; i += 256){
        int hh = i/56, ww = i - hh*56;
        dst[i] = sm[ww*57 + hh];
    }
}

// ---------------- 5. selective scan ----------------
// grid 256 = (b*4 + k)*4 + quarter; block 128 = 32 ch x 4 subs
__global__ __launch_bounds__(128) void scan_kernel(const float* __restrict__ dtw,
    const float* __restrict__ dtb, const float* __restrict__ alog, const float* __restrict__ Dp)
{
    __shared__ float dts [4*64];
    __shared__ float Uc  [32*65];
    __shared__ float du_s[32*65];
    __shared__ float p1_s[32*65];
    __shared__ float Pt  [64*40];    // [t][0..15]=B, [t][16..31]=C
    __shared__ float Yc  [32*65];
    __shared__ float dtw4s[32][4];
    __shared__ float dtbs[32], Dds[32];

    int tid = threadIdx.x;
    int blk = blockIdx.x;
    int q = blk & 3;
    int k = (blk >> 2) & 3;
    int b = blk >> 4;
    int ch = tid >> 2;
    int sub = tid & 3;
    int ng = sub*4;
    int d = q*32 + ch;
    int kd = k*DI_ + d;

    if (tid < 32){
        int kdl = k*DI_ + q*32 + tid;
        dtbs[tid] = dtb[kdl];
        Dds[tid]  = Dp[kdl];
        #pragma unroll
        for (int r = 0; r < 4; r++) dtw4s[tid][r] = dtw[kdl*4 + r];
    }
    float A2[4];
    bool structured = true;
    #pragma unroll
    for (int n = 0; n < 4; n++){
        A2[n] = -__expf(alog[kd*DST_ + ng + n]);
        if (fabsf(A2[n] + (float)(ng + n + 1)) > 1e-3f) structured = false;
    }
    float hst[4] = {0.f, 0.f, 0.f, 0.f};
    float Dd_own = Dp[kd];

    bool fwd = (k < 2);
    const float* usrc = ((k == 0) || (k == 2)) ? (g_xm + ((size_t)b*DI_ + d - ch)*LLC)
                                               : (g_xmT + ((size_t)b*DI_ + d - ch)*LLC);
    // base points at channel q*32+0; channel offset added per element
    const float* psrc;
    if (k == 0)      psrc = g_pj + ((size_t)b*KDIR*CX + 0*CX)*LLC;
    else if (k == 2) psrc = g_pj + ((size_t)b*KDIR*CX + 2*CX)*LLC;
    else if (k == 1) psrc = g_pjT + ((size_t)b*2*CX)*LLC;
    else             psrc = g_pjT + ((size_t)b*2*CX + CX)*LLC;
    float* yb = g_ys + (((size_t)(b*KDIR + k))*DI_ + q*32)*LLC;
    __syncthreads();

    for (int s0 = 0; s0 < LLC; s0 += 64){
        // ---- loads (coalesced) ----
        #pragma unroll
        for (int rr = 0; rr < 16; rr++){
            int i = tid + rr*128;          // 2048 items: Uc
            int cc = i >> 6, t = i & 63;
            int s = s0 + t;
            int gi = fwd ? s : (LLC-1-s);
            Uc[cc*65 + t] = usrc[(size_t)cc*LLC + gi];
        }
        {   // dt raw rows: 256 items
            int i = tid, i2 = tid + 128;
            int r = i >> 6, t = i & 63;
            int s = s0 + t;
            dts[i] = psrc[(size_t)r*LLC + (fwd ? s : (LLC-1-s))];
            r = i2 >> 6; t = i2 & 63; s = s0 + t;
            dts[i2] = psrc[(size_t)r*LLC + (fwd ? s : (LLC-1-s))];
        }
        #pragma unroll
        for (int rr = 0; rr < 16; rr++){
            int i = tid + rr*128;          // 2048 items: B/C rows 4..35
            int cc = i >> 6, t = i & 63;
            int s = s0 + t;
            Pt[t*40 + cc] = psrc[(size_t)(4+cc)*LLC + (fwd ? s : (LLC-1-s))];
        }
        __syncthreads();
        // ---- phase A: delta/du/p1 per (ch,t), deduped ----
        #pragma unroll
        for (int rr = 0; rr < 16; rr++){
            int i = tid + rr*128;
            int cc = i >> 6, t = i & 63;
            float dtr = dtbs[cc];
            dtr = fmaf(dts[t],       dtw4s[cc][0], dtr);
            dtr = fmaf(dts[64 + t],  dtw4s[cc][1], dtr);
            dtr = fmaf(dts[128 + t], dtw4s[cc][2], dtr);
            dtr = fmaf(dts[192 + t], dtw4s[cc][3], dtr);
            float e = __expf(dtr);
            float delta = (dtr > 20.f) ? dtr : __logf(1.f + e);
            du_s[cc*65 + t] = delta * Uc[cc*65 + t];
            p1_s[cc*65 + t] = __expf(-delta);
        }
        __syncthreads();
        // ---- serial scan over 64 steps ----
        for (int t = 0; t < 64; t++){
            float du = du_s[ch*65 + t];
            float p1 = p1_s[ch*65 + t];
            float4 Bv = *(const float4*)&Pt[t*40 + ng];
            float4 Cv = *(const float4*)&Pt[t*40 + 16 + ng];
            float pe0, pe1, pe2, pe3;
            if (structured){
                float p2 = p1*p1;
                float p4 = p2*p2;
                float p8 = p4*p4;
                float base = p1;
                if (sub & 1) base *= p4;
                if (sub & 2) base *= p8;
                pe0 = base;
                pe1 = base*p1;
                pe2 = base*p2;
                pe3 = pe2*p1;
            } else {
                // p1 = exp(-delta); pe_n = exp(delta*A2[n]) = p1^(-A2[n])
                pe0 = __powf(p1, -A2[0]);
                pe1 = __powf(p1, -A2[1]);
                pe2 = __powf(p1, -A2[2]);
                pe3 = __powf(p1, -A2[3]);
            }
            hst[0] = fmaf(pe0, hst[0], du*Bv.x);
            hst[1] = fmaf(pe1, hst[1], du*Bv.y);
            hst[2] = fmaf(pe2, hst[2], du*Bv.z);
            hst[3] = fmaf(pe3, hst[3], du*Bv.w);
            float y = hst[0]*Cv.x;
            y = fmaf(hst[1], Cv.y, y);
            y = fmaf(hst[2], Cv.z, y);
            y = fmaf(hst[3], Cv.w, y);
            y += __shfl_xor_sync(0xffffffffu, y, 1);
            y += __shfl_xor_sync(0xffffffffu, y, 2);
            if (sub == 0){
                float u = Uc[ch*65 + t];
                Yc[ch*65 + t] = fmaf(u, Dd_own, y);
            }
        }
        __syncthreads();
        #pragma unroll
        for (int rr = 0; rr < 16; rr++){
            int i = tid + rr*128;
            int cc = i >> 6, t = i & 63;
            yb[(size_t)cc*LLC + s0 + t] = Yc[cc*65 + t];
        }
        __syncthreads();
    }
}

// ---------------- 6. cross_merge + gelu ----------------
__global__ void mergegelu_kernel(void)
{
    __shared__ float sm1[56*57 + 8];
    __shared__ float sm3[56*57 + 8];
    int tid = threadIdx.x;
    int dch = blockIdx.x;
    int b   = blockIdx.y;
    const float* y0p = g_ys + (((size_t)(b*KDIR + 0))*DI_ + dch)*LLC;
    const float* y1p = g_ys + (((size_t)(b*KDIR + 1))*DI_ + dch)*LLC;
    const float* y2p = g_ys + (((size_t)(b*KDIR + 2))*DI_ + dch)*LLC;
    const float* y3p = g_ys + (((size_t)(b*KDIR + 3))*DI_ + dch)*LLC;
    for (int i = tid; i < LLC; i += 256){
        int hh = i / 56, ww = i - hh*56;
        sm1[hh*57 + ww] = y1p[i];
        sm3[hh*57 + ww] = y3p[i];
    }
    __syncthreads();
    float* op = g_ymg + ((size_t)b*DI_ + dch)*LLC;
    for (int p = tid; p < LLC; p += 256){
        int hh = p / 56, ww = p - hh*56;
        float v = y0p[p] + y2p[LLC-1-p] + sm1[ww*57 + hh] + sm3[(55-ww)*57 + (55-hh)];
        op[p] = fgelu(v);
    }
}

// ---------------- 7. pool / SE / residual1 ----------------
__global__ void pool_kernel(void)
{
    __shared__ float red[256];
    int bc = blockIdx.x;
    const float* yb = g_y + (size_t)bc*LLC;
    float s = 0.f;
    for (int i = threadIdx.x; i < LLC; i += 256) s += yb[i];
    red[threadIdx.x] = s;
    __syncthreads();
    for (int st = 128; st > 0; st >>= 1){
        if (threadIdx.x < st) red[threadIdx.x] += red[threadIdx.x + st];
        __syncthreads();
    }
    if (threadIdx.x == 0) g_pool[bc] = red[0]*(1.f/LLC);
}

__global__ void se_kernel(const float* __restrict__ w1, const float* __restrict__ b1,
    const float* __restrict__ w2, const float* __restrict__ b2)
{
    __shared__ float pv[DIMC];
    __shared__ float h1[32];
    int tid = threadIdx.x;
    int b = blockIdx.x;
    if (tid < DIMC) pv[tid] = g_pool[b*DIMC + tid];
    __syncthreads();
    if (tid < 32){
        float acc = b1[tid];
        #pragma unroll
        for (int c = 0; c < DIMC; c++) acc = fmaf(pv[c], w1[tid*DIMC + c], acc);
        h1[tid] = fmaxf(acc, 0.f);
    }
    __syncthreads();
    if (tid < DIMC){
        float acc = b2[tid];
        #pragma unroll
        for (int j = 0; j < 32; j++) acc = fmaf(h1[j], w2[tid*32 + j], acc);
        g_sse[b*DIMC + tid] = 1.f/(1.f + __expf(-acc));
    }
}

__global__ void resid1_kernel(const float* __restrict__ x, const float* __restrict__ gamma1)
{
    int gid = blockIdx.x*blockDim.x + threadIdx.x;
    int bc = gid / LLC;
    int c = bc % DIMC;
    g_xr[gid] = fmaf(gamma1[c]*g_sse[bc], g_y[gid], x[gid]);
}

// ---------------- 8. rms2d before MLP -> bf16 ----------------
// grid 784, block 256: g (4 groups of 32 ch) x 64 px
__global__ void rmsB_kernel(const float* __restrict__ gmlp)
{
    __shared__ float ssum[256];
    int tid = threadIdx.x;
    int g = tid >> 6, px = tid & 63;
    int gp = blockIdx.x*64 + px;
    int b = gp / LLC, p = gp - b*LLC;
    const float* xb = g_xr + ((size_t)b*DIMC + g*32)*LLC + p;
    float v[32];
    float s = 0.f;
    #pragma unroll
    for (int i = 0; i < 32; i++){ v[i] = xb[(size_t)i*LLC]; s += v[i]*v[i]; }
    ssum[tid] = s;
    __syncthreads();
    float tot = ssum[px] + ssum[64+px] + ssum[128+px] + ssum[192+px];
    float inv = rsqrtf(tot*(1.f/DIMC) + 1e-5f);
    __nv_bfloat16* ob = g_xnbf + ((size_t)b*DIMC + g*32)*LLC + p;
    #pragma unroll
    for (int i = 0; i < 32; i++)
        ob[(size_t)i*LLC] = __float2bfloat16(v[i]*inv*gmlp[g*32+i]);
}

// ---------------- 9. bf16 tensor-core GEMM for MLP ----------------
template<int MODE>
__global__ __launch_bounds__(256) void mma_mlp_kernel(
    const float* __restrict__ bias, const float* __restrict__ gamma2, float* __restrict__ outf)
{
    constexpr int K  = (MODE == 1) ? DIMC : HID4;
    __shared__ __nv_bfloat16 As[128*40];
    __shared__ __nv_bfloat16 Bs[32*136];
    int tid = threadIdx.x;
    int lane = tid & 31, wid = tid >> 5;
    int wm = wid >> 2, wn = wid & 3;
    int p0 = blockIdx.x*128;
    int m0 = blockIdx.y*128;
    int bz = blockIdx.z;
    const __nv_bfloat16* W = (MODE == 1) ? g_w1bf : g_w2bf;
    const __nv_bfloat16* X = (MODE == 1) ? g_xnbf : g_h;

    float acc[4][4][4];
    #pragma unroll
    for (int i = 0; i < 4; i++)
        #pragma unroll
        for (int j = 0; j < 4; j++)
            #pragma unroll
            for (int q = 0; q < 4; q++) acc[i][j][q] = 0.f;

    for (int kc = 0; kc < K; kc += 32){
        __syncthreads();
        {
            int i0 = tid*2;
            #pragma unroll
            for (int r = 0; r < 2; r++){
                int ii = i0 + r;
                int row = ii >> 2, seg = ii & 3;
                uint4 v = *(const uint4*)(W + (size_t)(m0 + row)*K + kc + seg*8);
                *(uint4*)(&As[row*40 + seg*8]) = v;
            }
        }
        {
            int kk = tid >> 3, pg = tid & 7;
            const __nv_bfloat16* src = X + ((size_t)bz*K + kc + kk)*LLC + p0 + pg*16;
            #pragma unroll
            for (int r = 0; r < 2; r++){
                int p = p0 + pg*16 + r*8;
                uint4 v = make_uint4(0u,0u,0u,0u);
                if (p < LLC) v = *(const uint4*)(src + r*8);
                *(uint4*)(&Bs[kk*136 + pg*16 + r*8]) = v;
            }
        }
        __syncthreads();
        #pragma unroll
        for (int ks = 0; ks < 2; ks++){
            int kk16 = ks*16;
            unsigned a[4][4], bfr[4][2];
            const unsigned* As32 = (const unsigned*)As;
            #pragma unroll
            for (int fm = 0; fm < 4; fm++){
                int row = wm*64 + fm*16 + (lane >> 2);
                int c = (kk16 >> 1) + (lane & 3);
                a[fm][0] = As32[row*20 + c];
                a[fm][1] = As32[(row+8)*20 + c];
                a[fm][2] = As32[row*20 + c + 4];
                a[fm][3] = As32[(row+8)*20 + c + 4];
            }
            const unsigned short* Bu = (const unsigned short*)Bs;
            #pragma unroll
            for (int fn = 0; fn < 4; fn++){
                int col = wn*32 + fn*8 + (lane >> 2);
                int kb = kk16 + (lane & 3)*2;
                unsigned lo0 = Bu[kb*136 + col],     hi0 = Bu[(kb+1)*136 + col];
                unsigned lo1 = Bu[(kb+8)*136 + col], hi1 = Bu[(kb+9)*136 + col];
                bfr[fn][0] = lo0 | (hi0 << 16);
                bfr[fn][1] = lo1 | (hi1 << 16);
            }
            #pragma unroll
            for (int fm = 0; fm < 4; fm++)
                #pragma unroll
                for (int fn = 0; fn < 4; fn++){
                    asm volatile(
                        "mma.sync.aligned.m16n8k16.row.col.f32.bf16.bf16.f32 "
                        "{%0,%1,%2,%3}, {%4,%5,%6,%7}, {%8,%9}, {%0,%1,%2,%3};"
                        : "+f"(acc[fm][fn][0]), "+f"(acc[fm][fn][1]),
                          "+f"(acc[fm][fn][2]), "+f"(acc[fm][fn][3])
                        : "r"(a[fm][0]), "r"(a[fm][1]), "r"(a[fm][2]), "r"(a[fm][3]),
                          "r"(bfr[fn][0]), "r"(bfr[fn][1]));
                }
        }
    }

    int r = lane >> 2, c2 = (lane & 3)*2;
    #pragma unroll
    for (int fm = 0; fm < 4; fm++){
        int m = m0 + wm*64 + fm*16 + r;
        float bv0 = bias[m], bv1 = bias[m+8];
        #pragma unroll
        for (int fn = 0; fn < 4; fn++){
            int p = p0 + wn*32 + fn*8 + c2;
            if (p < LLC){
                if (MODE == 1){
                    __nv_bfloat162 h2;
                    h2.x = __float2bfloat16(fgelu(acc[fm][fn][0] + bv0));
                    h2.y = __float2bfloat16(fgelu(acc[fm][fn][1] + bv0));
                    *(__nv_bfloat162*)&g_h[((size_t)bz*HID4 + m)*LLC + p] = h2;
                    __nv_bfloat162 h3;
                    h3.x = __float2bfloat16(fgelu(acc[fm][fn][2] + bv1));
                    h3.y = __float2bfloat16(fgelu(acc[fm][fn][3] + bv1));
                    *(__nv_bfloat162*)&g_h[((size_t)bz*HID4 + m + 8)*LLC + p] = h3;
                } else {
                    float g0 = gamma2[m], g1 = gamma2[m+8];
                    size_t o0 = ((size_t)bz*DIMC + m)*LLC + p;
                    size_t o1 = ((size_t)bz*DIMC + m + 8)*LLC + p;
                    float2 xr0 = *(const float2*)&g_xr[o0];
                    float2 xr1 = *(const float2*)&g_xr[o1];
                    float2 ov0, ov1;
                    ov0.x = fmaf(g0, acc[fm][fn][0] + bv0, xr0.x);
                    ov0.y = fmaf(g0, acc[fm][fn][1] + bv0, xr0.y);
                    ov1.x = fmaf(g1, acc[fm][fn][2] + bv1, xr1.x);
                    ov1.y = fmaf(g1, acc[fm][fn][3] + bv1, xr1.y);
                    *(float2*)&outf[o0] = ov0;
                    *(float2*)&outf[o1] = ov1;
                }
            }
        }
    }
}

// ---------------- launch ----------------
extern "C" void kernel_launch(void* const* d_in, const int* in_sizes, int n_in,
                              void* d_out, int out_size)
{
    const float* x      = (const float*)d_in[0];
    const float* wq     = (const float*)d_in[1];
    const float* wk     = (const float*)d_in[2];
    const float* wv     = (const float*)d_in[3];
    const float* wproj  = (const float*)d_in[4];
    const float* bproj  = (const float*)d_in[5];
    const float* gq     = (const float*)d_in[6];
    const float* gk     = (const float*)d_in[7];
    const float* gv     = (const float*)d_in[8];
    const float* gvm    = (const float*)d_in[9];
    const float* gmlp   = (const float*)d_in[10];
    const float* m_in_w = (const float*)d_in[11];
    const float* m_cw   = (const float*)d_in[12];
    const float* m_cb   = (const float*)d_in[13];
    const float* m_xp   = (const float*)d_in[14];
    const float* m_dtw  = (const float*)d_in[15];
    const float* m_dtb  = (const float*)d_in[16];
    const float* m_Alog = (const float*)d_in[17];
    const float* m_D    = (const float*)d_in[18];
    const float* m_outw = (const float*)d_in[19];
    const float* se_w1  = (const float*)d_in[20];
    const float* se_b1  = (const float*)d_in[21];
    const float* se_w2  = (const float*)d_in[22];
    const float* se_b2  = (const float*)d_in[23];
    const float* mlp_w1 = (const float*)d_in[24];
    const float* mlp_b1 = (const float*)d_in[25];
    const float* mlp_w2 = (const float*)d_in[26];
    const float* mlp_b2 = (const float*)d_in[27];
    const float* gamma1 = (const float*)d_in[28];
    const float* gamma2 = (const float*)d_in[29];
    float* out = (float*)d_out;

    void *p_xn1, *p_xn64, *p_qkv, *p_attno, *p_tmp, *p_xm, *p_ymg, *p_y, *p_wx, *p_wqkv;
    cudaGetSymbolAddress(&p_xn1,  g_xn1);
    cudaGetSymbolAddress(&p_xn64, g_xn64);
    cudaGetSymbolAddress(&p_qkv,  g_qkv);
    cudaGetSymbolAddress(&p_attno,g_attno);
    cudaGetSymbolAddress(&p_tmp,  g_tmp);
    cudaGetSymbolAddress(&p_xm,   g_xm);
    cudaGetSymbolAddress(&p_ymg,  g_ymg);
    cudaGetSymbolAddress(&p_y,    g_y);
    cudaGetSymbolAddress(&p_wx,   g_wx);
    cudaGetSymbolAddress(&p_wqkv, g_wqkv);

    int attn_bytes = (3*8*8*52 + 8*49*52)*4;
    cudaFuncSetAttribute(attncore_kernel, cudaFuncAttributeMaxDynamicSharedMemorySize, attn_bytes);

    wprep_kernel<<<256, 256>>>(mlp_w1, mlp_w2, m_xp, wq, wk, wv, gq, gk, gv);
    rms1_kernel<<<784, 256>>>(x, gvm);

    // attention branch
    gemm_f32_kernel<64, 64><<<dim3(25, 16, 3), 256>>>(
        (const float*)p_wqkv, (const float*)p_xn1, (float*)p_qkv, nullptr, 192, 0);
    attncore_kernel<<<1024, 256, attn_bytes>>>();
    gemm_f32_kernel<64, 64><<<dim3(25, 16, 1), 256>>>(
        wproj, (const float*)p_attno, (float*)p_y, bproj, 128, 0);

    // mamba branch
    gemm_f32_kernel<64, 64><<<dim3(25, 16, 2), 256>>>(
        m_in_w, (const float*)p_xn64, (float*)p_tmp, nullptr, 128, 0);
    dwconv_kernel<<<25088, 256>>>(m_cw, m_cb);
    gemm_f32_kernel<48, 128><<<dim3(25, 16, 3), 256>>>(
        (const float*)p_wx, (const float*)p_xm, (float*)g_pj, nullptr, 144, 0);
    transpose_kernel<<<3200, 256>>>();
    scan_kernel<<<256, 128>>>(m_dtw, m_dtb, m_Alog, m_D);
    mergegelu_kernel<<<dim3(128, 16), 256>>>();
    gemm_f32_kernel<64, 128><<<dim3(25, 16, 1), 256>>>(
        m_outw, (const float*)p_ymg, (float*)p_y, nullptr, 128, 64);

    // SE + residual 1
    pool_kernel<<<BBATCH*DIMC, 256>>>();
    se_kernel<<<BBATCH, 128>>>(se_w1, se_b1, se_w2, se_b2);
    resid1_kernel<<<25088, 256>>>(x, gamma1);

    // MLP (bf16 tensor cores) + residual 2
    rmsB_kernel<<<784, 256>>>(gmlp);
    mma_mlp_kernel<1><<<dim3(25, 4, 16), 256>>>(mlp_b1, nullptr, nullptr);
    mma_mlp_kernel<2><<<dim3(25, 1, 16), 256>>>(mlp_b2, gamma2, out);
}